// round 17
// baseline (speedup 1.0000x reference)
#include <cuda_runtime.h>
#include <cstdint>
#include <math.h>

#define IN_DIM   256
#define OUT_DIM  256
#define GRIDN    12      // NUM + 1 + 2K
#define NB       8       // NUM + K
#define BATCH    2048
#define BT       8       // batches per block
#define THREADS  256

// Transposed operands in device globals (allowed scratch):
//  g_coefT[o][k][i]  -> warp reads [i0..] coalesced
//  g_sbT/g_ssT[o][i] -> fused mask*scale
__device__ float g_coefT[OUT_DIM * NB * IN_DIM];   // 2 MB
__device__ float g_sbT[OUT_DIM * IN_DIM];
__device__ float g_ssT[OUT_DIM * IN_DIM];

__global__ void init_kernel(const float* __restrict__ sb,
                            const float* __restrict__ ssp,
                            const float* __restrict__ mask,
                            const float* __restrict__ coef,
                            float* __restrict__ ysum) {
    int idx = blockIdx.x * blockDim.x + threadIdx.x;   // 0 .. 524287
    if (idx < BATCH * OUT_DIM) ysum[idx] = 0.f;
    if (idx < IN_DIM * OUT_DIM) {
        int i = idx >> 8;
        int o = idx & 255;
        float m = mask[idx];
        g_sbT[o * IN_DIM + i] = m * sb[idx];
        g_ssT[o * IN_DIM + i] = m * ssp[idx];
    }
    if (idx < IN_DIM * OUT_DIM * NB) {
        // coef[i][o][k] -> g_coefT[o][k][i]
        int i   = idx >> 11;            // / (OUT_DIM*NB / ... ) = /2048
        int rem = idx & 2047;
        int o   = rem >> 3;
        int k   = rem & 7;
        g_coefT[(o * NB + k) * IN_DIM + i] = coef[idx];
    }
}

__global__ __launch_bounds__(THREADS, 2)
void kan_kernel(const float* __restrict__ x,
                const float* __restrict__ grid,
                float* __restrict__ out) {
    const int tid  = threadIdx.x;
    const int quad = tid & 63;       // i-quad
    const int bg   = tid >> 6;       // batch-pair group
    const int i0   = quad << 2;
    const int b0   = blockIdx.x * BT + bg * 2;

    // ---- B-spline basis for 2 batches x 4 dims (registers) ----
    float4 x4[2];
    x4[0] = *reinterpret_cast<const float4*>(x + (size_t)b0 * IN_DIM + i0);
    x4[1] = *reinterpret_cast<const float4*>(x + (size_t)(b0 + 1) * IN_DIM + i0);
    float xs[2][4] = {{x4[0].x, x4[0].y, x4[0].z, x4[0].w},
                      {x4[1].x, x4[1].y, x4[1].z, x4[1].w}};

    float bsp[2][NB][4];
    #pragma unroll
    for (int ii = 0; ii < 4; ii++) {
        const float* gr = grid + (size_t)(i0 + ii) * GRIDN;
        float g[GRIDN];
        #pragma unroll
        for (int j = 0; j < GRIDN; j++) g[j] = gr[j];
        #pragma unroll
        for (int bb = 0; bb < 2; bb++) {
            float xv = xs[bb][ii];
            float B[GRIDN - 1];
            #pragma unroll
            for (int j = 0; j < GRIDN - 1; j++)
                B[j] = (xv >= g[j] && xv < g[j + 1]) ? 1.f : 0.f;
            #pragma unroll
            for (int ki = 1; ki <= 3; ki++) {
                #pragma unroll
                for (int j = 0; j < GRIDN - 1; j++) {
                    if (j < GRIDN - 1 - ki) {
                        float left  = (xv - g[j]) / (g[j + ki] - g[j]);
                        float right = (g[j + ki + 1] - xv) / (g[j + ki + 1] - g[j + 1]);
                        B[j] = left * B[j] + right * B[j + 1];
                    }
                }
            }
            #pragma unroll
            for (int k = 0; k < NB; k++) bsp[bb][k][ii] = B[k];
        }
    }

    float base[2][4];
    #pragma unroll
    for (int bb = 0; bb < 2; bb++)
        #pragma unroll
        for (int ii = 0; ii < 4; ii++) {
            float xv = xs[bb][ii];
            base[bb][ii] = xv / (1.f + __expf(-xv));
        }

    float* ysum     = out;
    float* preacts  = out + (size_t)BATCH * OUT_DIM;
    float* postacts = preacts  + (size_t)BATCH * OUT_DIM * IN_DIM;
    float* postspl  = postacts + (size_t)BATCH * OUT_DIM * IN_DIM;

    const size_t rowbase0 = (size_t)b0 * OUT_DIM * IN_DIM + i0;

    // Barrier-free mainloop: per-o coef slice (8 KB) is L1-resident and
    // shared by all warps on the SM via cache hits. No smem, no syncs.
    for (int o = 0; o < OUT_DIM; o++) {
        const float* cT = g_coefT + (size_t)o * (NB * IN_DIM) + i0;

        // 8 coalesced LDG.128 (L1/L2 hits after first toucher)
        float4 c[NB];
        #pragma unroll
        for (int k = 0; k < NB; k++)
            c[k] = *reinterpret_cast<const float4*>(cT + k * IN_DIM);

        float4 sb4 = *reinterpret_cast<const float4*>(g_sbT + (size_t)o * IN_DIM + i0);
        float4 ss4 = *reinterpret_cast<const float4*>(g_ssT + (size_t)o * IN_DIM + i0);

        #pragma unroll
        for (int bb = 0; bb < 2; bb++) {
            float4 y4;
            y4.x = c[0].x * bsp[bb][0][0];
            y4.y = c[0].y * bsp[bb][0][1];
            y4.z = c[0].z * bsp[bb][0][2];
            y4.w = c[0].w * bsp[bb][0][3];
            #pragma unroll
            for (int k = 1; k < NB; k++) {
                y4.x += c[k].x * bsp[bb][k][0];
                y4.y += c[k].y * bsp[bb][k][1];
                y4.z += c[k].z * bsp[bb][k][2];
                y4.w += c[k].w * bsp[bb][k][3];
            }

            float4 yy4;
            yy4.x = sb4.x * base[bb][0] + ss4.x * y4.x;
            yy4.y = sb4.y * base[bb][1] + ss4.y * y4.y;
            yy4.z = sb4.z * base[bb][2] + ss4.z * y4.z;
            yy4.w = sb4.w * base[bb][3] + ss4.w * y4.w;

            size_t off = rowbase0 + (size_t)bb * (OUT_DIM * IN_DIM)
                                  + (size_t)o * IN_DIM;
            __stcs(reinterpret_cast<float4*>(postspl  + off), y4);
            __stcs(reinterpret_cast<float4*>(postacts + off), yy4);
            __stcs(reinterpret_cast<float4*>(preacts  + off), x4[bb]);

            // y_sum: warp butterfly + 1 atomic per (b,o) half-row
            float s = (yy4.x + yy4.y) + (yy4.z + yy4.w);
            #pragma unroll
            for (int d = 16; d > 0; d >>= 1)
                s += __shfl_xor_sync(0xffffffffu, s, d);
            if ((tid & 31) == 0)
                atomicAdd(ysum + (size_t)(b0 + bb) * OUT_DIM + o, s);
        }
    }
}

extern "C" void kernel_launch(void* const* d_in, const int* in_sizes, int n_in,
                              void* d_out, int out_size) {
    const float* x     = (const float*)d_in[0];
    const float* grid  = (const float*)d_in[1];
    const float* coef  = (const float*)d_in[2];
    const float* sb    = (const float*)d_in[3];
    const float* ssp   = (const float*)d_in[4];
    const float* mask  = (const float*)d_in[5];
    float* out = (float*)d_out;

    (void)in_sizes; (void)n_in; (void)out_size;

    int n = IN_DIM * OUT_DIM * NB;   // 524288 covers all init ranges
    init_kernel<<<(n + 255) / 256, 256>>>(sb, ssp, mask, coef, out);
    kan_kernel<<<BATCH / BT, THREADS>>>(x, grid, out);
}